// round 16
// baseline (speedup 1.0000x reference)
#include <cuda_runtime.h>
#include <cuda_bf16.h>
#include <cstdint>

// Problem dims
#define NTOK 65536
#define DIM  1024
#define HID  512
#define HHALF 256
#define NREG 16
#define MPER 4096

// ---------------- device scratch ----------------
__device__ __nv_bfloat16 g_H[(long)NTOK * HID];       // region_emb post-GELU (bf16)
__device__ __nv_bfloat16 g_Wt1[HID * DIM];            // W1^T  [512,1024] bf16
__device__ __nv_bfloat16 g_Wt2[HHALF * HID];          // Wa1^T [256,512] bf16
__device__ float g_scores_t[NTOK];                    // region-transposed: [r][m]
__device__ float g_stats[32];                         // [0:16) max, [16:32) sumexp
__device__ float g_pmax[128];                         // per (r, chunk-of-512) max
__device__ float g_psum[128];                         // per (r, chunk) sumexp(local max)
__device__ float g_se[NREG * HID];                    // slide_emb
__device__ float g_sattn[NREG];                       // slide attention raw scores
__device__ float2 g_pp[512 * NREG * 256];             // pooling partials [blk][r][cpair]
__device__ float2 g_pp2[4 * NREG * 256];              // second-level pooling partials

__device__ __forceinline__ float gelu_exact(float v) {
    return 0.5f * v * (1.0f + erff(v * 0.7071067811865475f));
}

// ---------------- helpers ----------------
__device__ __forceinline__ uint32_t smem_u32(const void* p) {
    uint32_t a;
    asm("{ .reg .u64 t; cvta.to.shared.u64 t, %1; cvt.u32.u64 %0, t; }" : "=r"(a) : "l"(p));
    return a;
}
__device__ __forceinline__ uint32_t bf2u(__nv_bfloat162 v) { return *reinterpret_cast<uint32_t*>(&v); }

#define SWZ(o) ((o) ^ (((o) >> 3) & 0x70))
#define CP16(d, s) asm volatile("cp.async.cg.shared.global [%0],[%1],16;" :: "r"(d), "l"(s))
#define CP_COMMIT  asm volatile("cp.async.commit_group;" ::: "memory")
#define CP_WAIT0   asm volatile("cp.async.wait_group 0;" ::: "memory")
#define CP_WAIT1   asm volatile("cp.async.wait_group 1;" ::: "memory")

// ---------------- weight transpose+convert: fp32 [K,N] -> bf16 [N,K] ---------
__global__ __launch_bounds__(256)
void transpose_conv(const float* __restrict__ src, __nv_bfloat16* __restrict__ dst,
                    int K, int N)
{
    __shared__ float t[32][33];
    int nb = blockIdx.x * 32, kb = blockIdx.y * 32;
    int x = threadIdx.x & 31, y = threadIdx.x >> 5;
    #pragma unroll
    for (int i = 0; i < 32; i += 8) t[y + i][x] = src[(long)(kb + y + i) * N + nb + x];
    __syncthreads();
    #pragma unroll
    for (int i = 0; i < 32; i += 8)
        dst[(long)(nb + y + i) * K + kb + x] = __float2bfloat16(t[x][y + i]);
}

// ---------------- unified mma.sync GEMM ---------------------------------------
// CTA tile 128x256, 512 threads (16 warps, 4m x 4n), warp tile 32x64, BK=64,
// 3-stage cp.async pipeline + DOUBLE-BUFFERED ldmatrix fragments (kk pipeline).
// MODE 0: A = emb fp32 (inline LDG+cvt->STS), B = g_Wt1; GELU -> g_H.
// MODE 1: A = g_H bf16 (cp.async), B = g_Wt2; full-N tanh-dot -> direct scores.
#define SSTAGE 49152               // A 128x64 bf16 (16KB) + B 256x64 bf16 (32KB)
#define SMEM_REQ (3 * SSTAGE + 4096)

template<int KDIM, int MODE>
__global__ __launch_bounds__(512, 1)
void mma_gemm(const float* __restrict__ Af, const float* __restrict__ biasp,
              const float* __restrict__ Wa2p, const float* __restrict__ ba2p)
{
    extern __shared__ unsigned char smem[];
    constexpr int NCH = KDIM / 64;
    const int tid = threadIdx.x, warp = tid >> 5, lane = tid & 31;
    const int wm = warp >> 2, wn = warp & 3;
    const long row0 = (long)blockIdx.y * 128;
    const int col0 = blockIdx.x * 256;

    uint32_t sbb = smem_u32(smem);
    float* bias_s = (float*)(smem + 3 * SSTAGE);      // 256 floats
    float* w2_s = bias_s + 256;                        // 256 floats
    float* sp = w2_s + 256;                            // 512 floats (MODE1 partials)
    if (tid < 256) {
        bias_s[tid] = biasp[col0 + tid];
        if (MODE == 1) w2_s[tid] = Wa2p[tid];
    }

    const __nv_bfloat16* Bt = (MODE == 0) ? g_Wt1 : g_Wt2;

    auto stage = [&](int sbuf, int kc) {
        if (MODE == 0) {
            // A fp32 LDG -> bf16 STS (temps live only inside)
            int arow = tid >> 2, aq = tid & 3;
            const float4* s4 = (const float4*)(Af + (row0 + arow) * (long)KDIM + kc * 64 + aq * 16);
            float4 v0 = s4[0], v1 = s4[1], v2 = s4[2], v3 = s4[3];
            uint4 p0, p1;
            p0.x = bf2u(__floats2bfloat162_rn(v0.x, v0.y));
            p0.y = bf2u(__floats2bfloat162_rn(v0.z, v0.w));
            p0.z = bf2u(__floats2bfloat162_rn(v1.x, v1.y));
            p0.w = bf2u(__floats2bfloat162_rn(v1.z, v1.w));
            p1.x = bf2u(__floats2bfloat162_rn(v2.x, v2.y));
            p1.y = bf2u(__floats2bfloat162_rn(v2.z, v2.w));
            p1.z = bf2u(__floats2bfloat162_rn(v3.x, v3.y));
            p1.w = bf2u(__floats2bfloat162_rn(v3.z, v3.w));
            uint32_t o = (uint32_t)(arow * 128 + aq * 32);
            *(uint4*)(smem + sbuf * SSTAGE + SWZ(o)) = p0;
            *(uint4*)(smem + sbuf * SSTAGE + SWZ(o + 16)) = p1;
        } else {
            uint32_t ab = sbb + sbuf * SSTAGE;
            #pragma unroll
            for (int i = 0; i < 2; i++) {
                int u = tid + 512 * i, row = u >> 3, cu = u & 7;
                CP16(ab + SWZ((uint32_t)(row * 128 + cu * 16)),
                     (const void*)(g_H + (row0 + row) * (long)KDIM + kc * 64 + cu * 8));
            }
        }
        uint32_t bb = sbb + sbuf * SSTAGE + 16384;
        #pragma unroll
        for (int i = 0; i < 4; i++) {
            int u = tid + 512 * i, row = u >> 3, cu = u & 7;
            CP16(bb + SWZ((uint32_t)(row * 128 + cu * 16)),
                 (const void*)(Bt + (col0 + row) * (long)KDIM + kc * 64 + cu * 8));
        }
    };

    float acc[2][8][4];
    #pragma unroll
    for (int mi = 0; mi < 2; mi++)
        #pragma unroll
        for (int ni = 0; ni < 8; ni++)
            #pragma unroll
            for (int q = 0; q < 4; q++) acc[mi][ni][q] = 0.0f;

    // frag double buffers
    uint32_t afb[2][2][4], bfb[2][8][2];

    auto ldA = [&](uint32_t Ab, int kk, uint32_t af[2][4]) {
        #pragma unroll
        for (int mi = 0; mi < 2; mi++) {
            int row = wm * 32 + mi * 16 + (lane & 15);
            uint32_t ad = Ab + SWZ((uint32_t)(row * 128 + kk * 32 + ((lane >> 4) << 4)));
            asm volatile("ldmatrix.sync.aligned.m8n8.x4.shared.b16 {%0,%1,%2,%3},[%4];"
                : "=r"(af[mi][0]), "=r"(af[mi][1]), "=r"(af[mi][2]), "=r"(af[mi][3])
                : "r"(ad));
        }
    };
    auto ldB = [&](uint32_t Bb, int kk, uint32_t bfr[8][2]) {
        #pragma unroll
        for (int nj = 0; nj < 4; nj++) {
            int row = wn * 64 + nj * 16 + ((lane >> 4) << 3) + (lane & 7);
            uint32_t bd = Bb + SWZ((uint32_t)(row * 128 + kk * 32 + (((lane >> 3) & 1) << 4)));
            asm volatile("ldmatrix.sync.aligned.m8n8.x4.shared.b16 {%0,%1,%2,%3},[%4];"
                : "=r"(bfr[2*nj][0]), "=r"(bfr[2*nj][1]),
                  "=r"(bfr[2*nj+1][0]), "=r"(bfr[2*nj+1][1])
                : "r"(bd));
        }
    };

    // prologue: 2 chunks in flight
    stage(0, 0); CP_COMMIT;
    stage(1, 1); CP_COMMIT;

    #pragma unroll 1
    for (int kc = 0; kc < NCH; kc++) {
        const int s = kc % 3;
        if (kc + 1 < NCH) { CP_WAIT1; } else { CP_WAIT0; }
        __syncthreads();

        uint32_t Ab = sbb + s * SSTAGE, Bb = Ab + 16384;
        // first frag batch of this chunk
        ldA(Ab, 0, afb[0]); ldB(Bb, 0, bfb[0]);

        // stage next chunk (cp.async issues overlap frag loads + MMAs)
        if (kc + 2 < NCH) { stage((kc + 2) % 3, kc + 2); CP_COMMIT; }

        #pragma unroll
        for (int kk = 0; kk < 4; kk++) {
            const int cur = kk & 1, nxt = cur ^ 1;
            if (kk < 3) { ldA(Ab, kk + 1, afb[nxt]); ldB(Bb, kk + 1, bfb[nxt]); }
            #pragma unroll
            for (int mi = 0; mi < 2; mi++)
                #pragma unroll
                for (int ni = 0; ni < 8; ni++)
                    asm volatile("mma.sync.aligned.m16n8k16.row.col.f32.bf16.bf16.f32 "
                        "{%0,%1,%2,%3},{%4,%5,%6,%7},{%8,%9},{%0,%1,%2,%3};"
                        : "+f"(acc[mi][ni][0]), "+f"(acc[mi][ni][1]),
                          "+f"(acc[mi][ni][2]), "+f"(acc[mi][ni][3])
                        : "r"(afb[cur][mi][0]), "r"(afb[cur][mi][1]),
                          "r"(afb[cur][mi][2]), "r"(afb[cur][mi][3]),
                          "r"(bfb[cur][ni][0]), "r"(bfb[cur][ni][1]));
        }
    }

    // ---- epilogue ----
    if (MODE == 0) {
        #pragma unroll
        for (int mi = 0; mi < 2; mi++) {
            long r0 = row0 + wm * 32 + mi * 16 + (lane >> 2);
            #pragma unroll
            for (int ni = 0; ni < 8; ni++) {
                int cc = wn * 64 + ni * 8 + ((lane & 3) << 1);
                float b0 = bias_s[cc], b1 = bias_s[cc + 1];
                float* c = acc[mi][ni];
                uint32_t p0 = bf2u(__floats2bfloat162_rn(gelu_exact(c[0] + b0), gelu_exact(c[1] + b1)));
                uint32_t p1 = bf2u(__floats2bfloat162_rn(gelu_exact(c[2] + b0), gelu_exact(c[3] + b1)));
                *(uint32_t*)(g_H + r0 * HID + col0 + cc) = p0;
                *(uint32_t*)(g_H + (r0 + 8) * HID + col0 + cc) = p1;
            }
        }
    } else {
        #pragma unroll
        for (int mi = 0; mi < 2; mi++) {
            float s0 = 0.f, s1 = 0.f;
            #pragma unroll
            for (int ni = 0; ni < 8; ni++) {
                int cc = wn * 64 + ni * 8 + ((lane & 3) << 1);
                float b0 = bias_s[cc], b1 = bias_s[cc + 1];
                float w0 = w2_s[cc], w1 = w2_s[cc + 1];
                float* c = acc[mi][ni];
                s0 += tanhf(c[0] + b0) * w0 + tanhf(c[1] + b1) * w1;
                s1 += tanhf(c[2] + b0) * w0 + tanhf(c[3] + b1) * w1;
            }
            s0 += __shfl_xor_sync(0xffffffffu, s0, 1);
            s0 += __shfl_xor_sync(0xffffffffu, s0, 2);
            s1 += __shfl_xor_sync(0xffffffffu, s1, 1);
            s1 += __shfl_xor_sync(0xffffffffu, s1, 2);
            if ((lane & 3) == 0) {
                int lr = wm * 32 + mi * 16 + (lane >> 2);
                sp[lr * 4 + wn] = s0;
                sp[(lr + 8) * 4 + wn] = s1;
            }
        }
        __syncthreads();
        if (tid < 128) {
            float sc = sp[tid * 4] + sp[tid * 4 + 1] + sp[tid * 4 + 2] + sp[tid * 4 + 3] + ba2p[0];
            long t = row0 + tid;
            g_scores_t[(t & 15) * MPER + (t >> 4)] = sc;
        }
    }
}

// ---------------- softmax stats, two-phase ------------------------------------
__global__ __launch_bounds__(256)
void stats_p1()
{
    int r = blockIdx.x, q = blockIdx.y, tid = threadIdx.x;
    __shared__ float red[256];
    const float* spt = g_scores_t + r * MPER + q * 512;
    float v0 = spt[tid], v1 = spt[tid + 256];
    red[tid] = fmaxf(v0, v1);
    __syncthreads();
    for (int s = 128; s; s >>= 1) { if (tid < s) red[tid] = fmaxf(red[tid], red[tid + s]); __syncthreads(); }
    float mx = red[0];
    __syncthreads();
    red[tid] = expf(v0 - mx) + expf(v1 - mx);
    __syncthreads();
    for (int s = 128; s; s >>= 1) { if (tid < s) red[tid] += red[tid + s]; __syncthreads(); }
    if (tid == 0) { g_pmax[r * 8 + q] = mx; g_psum[r * 8 + q] = red[0]; }
}

__global__ __launch_bounds__(128)
void stats_p2()
{
    __shared__ float m[128], s[128];
    int tid = threadIdx.x;
    m[tid] = g_pmax[tid]; s[tid] = g_psum[tid];
    __syncthreads();
    if (tid < NREG) {
        float M = -1e30f;
        #pragma unroll
        for (int j = 0; j < 8; j++) M = fmaxf(M, m[tid * 8 + j]);
        float S = 0.f;
        #pragma unroll
        for (int j = 0; j < 8; j++) S += s[tid * 8 + j] * expf(m[tid * 8 + j] - M);
        g_stats[tid] = M; g_stats[16 + tid] = S;
    }
}

// ---------------- pooling: coalesced partials over token blocks ---------------
__global__ __launch_bounds__(256)
void pool_partial()
{
    __shared__ float wts[128];
    int blk = blockIdx.x, tid = threadIdx.x;
    long base = (long)blk * 128;
    if (tid < 128) {
        long t = base + tid;
        int r = (int)(t & 15);
        wts[tid] = expf(g_scores_t[r * MPER + (t >> 4)] - g_stats[r]);
    }
    __syncthreads();
    int c = tid;
    #pragma unroll 1
    for (int r = 0; r < NREG; r++) {
        float a0 = 0.f, a1 = 0.f;
        #pragma unroll
        for (int i = 0; i < 8; i++) {
            int lr = r + i * 16;
            uint32_t u = *(const uint32_t*)(g_H + (base + lr) * HID + 2 * c);
            __nv_bfloat162 h2 = *reinterpret_cast<__nv_bfloat162*>(&u);
            float w = wts[lr];
            a0 += w * __bfloat162float(h2.x);
            a1 += w * __bfloat162float(h2.y);
        }
        g_pp[(blk * NREG + r) * 256 + c] = make_float2(a0, a1);
    }
}

__global__ __launch_bounds__(256)
void pool_reduce4()
{
    int r = blockIdx.x, q = blockIdx.y, c = threadIdx.x;
    float a0 = 0.f, a1 = 0.f;
    #pragma unroll 4
    for (int blk = q * 128; blk < q * 128 + 128; blk++) {
        float2 v = g_pp[(blk * NREG + r) * 256 + c];
        a0 += v.x; a1 += v.y;
    }
    g_pp2[(q * NREG + r) * 256 + c] = make_float2(a0, a1);
}

// ---------------- slide encoder + attention score, one CTA per region ---------
__global__ __launch_bounds__(512)
void slide_enc(const float* __restrict__ Ws,  const float* __restrict__ bs,
               const float* __restrict__ Wsa1,const float* __restrict__ bsa1,
               const float* __restrict__ Wsa2,const float* __restrict__ bsa2)
{
    __shared__ float rf[HID];
    __shared__ float se[HID];
    __shared__ float part[512];
    int r = blockIdx.x, tid = threadIdx.x;

    {
        float inv = 1.0f / g_stats[16 + r];
        int cp = tid >> 1;
        float a = 0.f;
        #pragma unroll
        for (int q = 0; q < 4; q++) {
            float2 v = g_pp2[(q * NREG + r) * 256 + cp];
            a += (tid & 1) ? v.y : v.x;
        }
        rf[tid] = a * inv;
    }
    __syncthreads();

    float acc = 0.f;
    #pragma unroll 8
    for (int k = 0; k < HID; k++) acc += rf[k] * Ws[k * HID + tid];
    float sev = gelu_exact(acc + bs[tid]);
    se[tid] = sev;
    g_se[r * HID + tid] = sev;
    __syncthreads();

    int j = tid & 255, h = tid >> 8;
    float p = 0.f;
    #pragma unroll 8
    for (int k = h * 256; k < h * 256 + 256; k++) p += se[k] * Wsa1[k * HHALF + j];
    part[tid] = p;
    __syncthreads();
    if (tid < 256)
        part[tid] = tanhf(part[tid] + part[tid + 256] + bsa1[tid]) * Wsa2[tid];
    __syncthreads();
    for (int s = 128; s; s >>= 1) { if (tid < s) part[tid] += part[tid + s]; __syncthreads(); }
    if (tid == 0) g_sattn[r] = part[0] + bsa2[0];
}

// ---------------- final: softmax-16 + slide_rep + classifier ------------------
__global__ __launch_bounds__(512)
void tail_final(const float* __restrict__ Wc1, const float* __restrict__ bc1,
                const float* __restrict__ Wc2, const float* __restrict__ bc2,
                float* __restrict__ out)
{
    __shared__ float w[NREG];
    __shared__ float srep[HID];
    __shared__ float c1[HHALF];
    __shared__ float red[64];
    int tid = threadIdx.x;

    if (tid == 0) {
        float mx = -1e30f;
        for (int r = 0; r < NREG; r++) mx = fmaxf(mx, g_sattn[r]);
        float s = 0.f;
        for (int r = 0; r < NREG; r++) { w[r] = expf(g_sattn[r] - mx); s += w[r]; }
        for (int r = 0; r < NREG; r++) w[r] /= s;
    }
    __syncthreads();

    float a = 0.f;
    #pragma unroll
    for (int r = 0; r < NREG; r++) a += w[r] * g_se[r * HID + tid];
    srep[tid] = a;
    __syncthreads();

    if (tid < HHALF) {
        float acc = 0.f;
        #pragma unroll 8
        for (int k = 0; k < HID; k++) acc += srep[k] * Wc1[k * HHALF + tid];
        c1[tid] = gelu_exact(acc + bc1[tid]);
    }
    __syncthreads();

    if (tid < 64) {
        int o = tid & 1, p = tid >> 1;
        float acc = 0.f;
        for (int k = p; k < HHALF; k += 32) acc += c1[k] * Wc2[k * 2 + o];
        red[tid] = acc;
    }
    __syncthreads();
    if (tid < 2) {
        float acc = bc2[tid];
        #pragma unroll
        for (int p = 0; p < 32; p++) acc += red[p * 2 + tid];
        out[tid] = acc;
    }
}

// ---------------- launch ------------------------------------------------------
extern "C" void kernel_launch(void* const* d_in, const int* in_sizes, int n_in,
                              void* d_out, int out_size)
{
    const float* emb  = (const float*)d_in[0];
    const float* W1   = (const float*)d_in[1];
    const float* b1   = (const float*)d_in[2];
    const float* Wa1  = (const float*)d_in[3];
    const float* ba1  = (const float*)d_in[4];
    const float* Wa2  = (const float*)d_in[5];
    const float* ba2  = (const float*)d_in[6];
    const float* Ws   = (const float*)d_in[7];
    const float* bs   = (const float*)d_in[8];
    const float* Wsa1 = (const float*)d_in[9];
    const float* bsa1 = (const float*)d_in[10];
    const float* Wsa2 = (const float*)d_in[11];
    const float* bsa2 = (const float*)d_in[12];
    const float* Wc1  = (const float*)d_in[13];
    const float* bc1  = (const float*)d_in[14];
    const float* Wc2  = (const float*)d_in[15];
    const float* bc2  = (const float*)d_in[16];
    float* out = (float*)d_out;

    cudaFuncSetAttribute(mma_gemm<DIM, 0>, cudaFuncAttributeMaxDynamicSharedMemorySize, SMEM_REQ);
    cudaFuncSetAttribute(mma_gemm<HID, 1>, cudaFuncAttributeMaxDynamicSharedMemorySize, SMEM_REQ);

    __nv_bfloat16 *wt1, *wt2;
    cudaGetSymbolAddress((void**)&wt1, g_Wt1);
    cudaGetSymbolAddress((void**)&wt2, g_Wt2);
    transpose_conv<<<dim3(HID / 32, DIM / 32), 256>>>(W1, wt1, DIM, HID);
    transpose_conv<<<dim3(HHALF / 32, HID / 32), 256>>>(Wa1, wt2, HID, HHALF);

    // K1: region encoder (65536x1024 @ 1024x512) + GELU -> g_H
    mma_gemm<DIM, 0><<<dim3(2, NTOK / 128), 512, SMEM_REQ>>>(emb, b1, nullptr, nullptr);
    // K2: attention hidden (65536x512 @ 512x256) + fused tanh-dot -> direct scores
    mma_gemm<HID, 1><<<dim3(1, NTOK / 128), 512, SMEM_REQ>>>(nullptr, ba1, Wa2, ba2);

    stats_p1<<<dim3(NREG, 8), 256>>>();
    stats_p2<<<1, 128>>>();
    pool_partial<<<512, 256>>>();
    pool_reduce4<<<dim3(NREG, 4), 256>>>();
    slide_enc<<<NREG, 512>>>(Ws, bs, Wsa1, bsa1, Wsa2, bsa2);
    tail_final<<<1, 512>>>(Wc1, bc1, Wc2, bc2, out);
}

// round 17
// speedup vs baseline: 1.0534x; 1.0534x over previous
#include <cuda_runtime.h>
#include <cuda_bf16.h>
#include <cstdint>

// Problem dims
#define NTOK 65536
#define DIM  1024
#define HID  512
#define HHALF 256
#define NREG 16
#define MPER 4096

// ---------------- device scratch ----------------
__device__ __nv_bfloat16 g_H[(long)NTOK * HID];       // region_emb post-GELU (bf16)
__device__ __nv_bfloat16 g_Wt1[HID * DIM];            // W1^T  [512,1024] bf16
__device__ __nv_bfloat16 g_Wt2[HHALF * HID];          // Wa1^T [256,512] bf16
__device__ float g_scores_t[NTOK];                    // region-transposed: [r][m]
__device__ float g_stats[32];                         // [0:16) max, [16:32) sumexp
__device__ float g_pmax[128];                         // per (r, chunk-of-512) max
__device__ float g_psum[128];                         // per (r, chunk) sumexp(local max)
__device__ float g_se[NREG * HID];                    // slide_emb
__device__ float g_sattn[NREG];                       // slide attention raw scores
__device__ float2 g_pp[512 * NREG * 256];             // pooling partials [blk][r][cpair]
__device__ float2 g_pp2[4 * NREG * 256];              // second-level pooling partials

__device__ __forceinline__ float gelu_exact(float v) {
    return 0.5f * v * (1.0f + erff(v * 0.7071067811865475f));
}

// ---------------- helpers ----------------
__device__ __forceinline__ uint32_t smem_u32(const void* p) {
    uint32_t a;
    asm("{ .reg .u64 t; cvta.to.shared.u64 t, %1; cvt.u32.u64 %0, t; }" : "=r"(a) : "l"(p));
    return a;
}
__device__ __forceinline__ uint32_t bf2u(__nv_bfloat162 v) { return *reinterpret_cast<uint32_t*>(&v); }

#define SWZ(o) ((o) ^ (((o) >> 3) & 0x70))
#define CP16(d, s) asm volatile("cp.async.cg.shared.global [%0],[%1],16;" :: "r"(d), "l"(s))
#define CP_COMMIT  asm volatile("cp.async.commit_group;" ::: "memory")
#define CP_WAIT0   asm volatile("cp.async.wait_group 0;" ::: "memory")
#define CP_WAIT1   asm volatile("cp.async.wait_group 1;" ::: "memory")

// ---------------- weight transpose+convert: fp32 [K,N] -> bf16 [N,K] ---------
__global__ __launch_bounds__(256)
void transpose_conv(const float* __restrict__ src, __nv_bfloat16* __restrict__ dst,
                    int K, int N)
{
    __shared__ float t[32][33];
    int nb = blockIdx.x * 32, kb = blockIdx.y * 32;
    int x = threadIdx.x & 31, y = threadIdx.x >> 5;
    #pragma unroll
    for (int i = 0; i < 32; i += 8) t[y + i][x] = src[(long)(kb + y + i) * N + nb + x];
    __syncthreads();
    #pragma unroll
    for (int i = 0; i < 32; i += 8)
        dst[(long)(nb + y + i) * K + kb + x] = __float2bfloat16(t[x][y + i]);
}

// ---------------- unified mma.sync GEMM (round-14 proven config) --------------
// CTA tile 128x256, 512 threads (16 warps, 4m x 4n), warp tile 32x64, BK=64,
// 3-stage pipeline. MODE 0: A-LDG prefetched into regs one chunk early.
// MODE 1: A = g_H bf16 via cp.async. Full-N tanh-dot epilogue -> direct scores.
#define SSTAGE 49152               // A 128x64 bf16 (16KB) + B 256x64 bf16 (32KB)
#define SMEM_REQ (3 * SSTAGE + 4096)

template<int KDIM, int MODE>
__global__ __launch_bounds__(512, 1)
void mma_gemm(const float* __restrict__ Af, const float* __restrict__ biasp,
              const float* __restrict__ Wa2p, const float* __restrict__ ba2p)
{
    extern __shared__ unsigned char smem[];
    constexpr int NCH = KDIM / 64;
    const int tid = threadIdx.x, warp = tid >> 5, lane = tid & 31;
    const int wm = warp >> 2, wn = warp & 3;
    const long row0 = (long)blockIdx.y * 128;
    const int col0 = blockIdx.x * 256;

    uint32_t sbb = smem_u32(smem);
    float* bias_s = (float*)(smem + 3 * SSTAGE);      // 256 floats
    float* w2_s = bias_s + 256;                        // 256 floats
    float* sp = w2_s + 256;                            // 512 floats (MODE1 partials)
    if (tid < 256) {
        bias_s[tid] = biasp[col0 + tid];
        if (MODE == 1) w2_s[tid] = Wa2p[tid];
    }

    const __nv_bfloat16* Bt = (MODE == 0) ? g_Wt1 : g_Wt2;

    float4 areg[4];                 // MODE 0: prefetched A (row tid>>2, 16 cols)
    const int arow = tid >> 2, aq = tid & 3;

    auto ldgA = [&](int kc) {       // MODE 0 only: global fp32 -> regs
        const float4* s4 = (const float4*)(Af + (row0 + arow) * (long)KDIM + kc * 64 + aq * 16);
        areg[0] = s4[0]; areg[1] = s4[1]; areg[2] = s4[2]; areg[3] = s4[3];
    };
    auto stsA = [&](int sbuf) {     // MODE 0 only: regs -> bf16 smem
        uint4 p0, p1;
        p0.x = bf2u(__floats2bfloat162_rn(areg[0].x, areg[0].y));
        p0.y = bf2u(__floats2bfloat162_rn(areg[0].z, areg[0].w));
        p0.z = bf2u(__floats2bfloat162_rn(areg[1].x, areg[1].y));
        p0.w = bf2u(__floats2bfloat162_rn(areg[1].z, areg[1].w));
        p1.x = bf2u(__floats2bfloat162_rn(areg[2].x, areg[2].y));
        p1.y = bf2u(__floats2bfloat162_rn(areg[2].z, areg[2].w));
        p1.z = bf2u(__floats2bfloat162_rn(areg[3].x, areg[3].y));
        p1.w = bf2u(__floats2bfloat162_rn(areg[3].z, areg[3].w));
        uint32_t o = (uint32_t)(arow * 128 + aq * 32);
        *(uint4*)(smem + sbuf * SSTAGE + SWZ(o)) = p0;
        *(uint4*)(smem + sbuf * SSTAGE + SWZ(o + 16)) = p1;
    };
    auto cpA = [&](int sbuf, int kc) {  // MODE 1 only
        uint32_t ab = sbb + sbuf * SSTAGE;
        #pragma unroll
        for (int i = 0; i < 2; i++) {
            int u = tid + 512 * i, row = u >> 3, cu = u & 7;
            CP16(ab + SWZ((uint32_t)(row * 128 + cu * 16)),
                 (const void*)(g_H + (row0 + row) * (long)KDIM + kc * 64 + cu * 8));
        }
    };
    auto cpB = [&](int sbuf, int kc) {
        uint32_t bb = sbb + sbuf * SSTAGE + 16384;
        #pragma unroll
        for (int i = 0; i < 4; i++) {
            int u = tid + 512 * i, row = u >> 3, cu = u & 7;
            CP16(bb + SWZ((uint32_t)(row * 128 + cu * 16)),
                 (const void*)(Bt + (col0 + row) * (long)KDIM + kc * 64 + cu * 8));
        }
    };

    float acc[2][8][4];
    #pragma unroll
    for (int mi = 0; mi < 2; mi++)
        #pragma unroll
        for (int ni = 0; ni < 8; ni++)
            #pragma unroll
            for (int q = 0; q < 4; q++) acc[mi][ni][q] = 0.0f;

    // prologue
    if (MODE == 0) {
        ldgA(0); cpB(0, 0); CP_COMMIT; stsA(0);
        ldgA(1); cpB(1, 1); CP_COMMIT; stsA(1);
        ldgA(2);                       // NCH = 16
    } else {
        cpA(0, 0); cpB(0, 0); CP_COMMIT;
        cpA(1, 1); cpB(1, 1); CP_COMMIT;
    }

    #pragma unroll 1
    for (int kc = 0; kc < NCH; kc++) {
        const int s = kc % 3;
        if (kc + 1 < NCH) { CP_WAIT1; } else { CP_WAIT0; }
        __syncthreads();
        if (kc + 2 < NCH) {
            if (MODE == 0) {
                cpB((kc + 2) % 3, kc + 2);      // async copies in flight first
                stsA((kc + 2) % 3);             // buffer freed by the sync above
                if (kc + 3 < NCH) ldgA(kc + 3); // prefetch (hidden under MMA)
            } else {
                cpA((kc + 2) % 3, kc + 2);
                cpB((kc + 2) % 3, kc + 2);
            }
            CP_COMMIT;
        }

        uint32_t Ab = sbb + s * SSTAGE, Bb = Ab + 16384;
        #pragma unroll
        for (int kk = 0; kk < 4; kk++) {
            uint32_t af[2][4], bfr[8][2];
            #pragma unroll
            for (int mi = 0; mi < 2; mi++) {
                int row = wm * 32 + mi * 16 + (lane & 15);
                uint32_t ad = Ab + SWZ((uint32_t)(row * 128 + kk * 32 + ((lane >> 4) << 4)));
                asm volatile("ldmatrix.sync.aligned.m8n8.x4.shared.b16 {%0,%1,%2,%3},[%4];"
                    : "=r"(af[mi][0]), "=r"(af[mi][1]), "=r"(af[mi][2]), "=r"(af[mi][3])
                    : "r"(ad));
            }
            #pragma unroll
            for (int nj = 0; nj < 4; nj++) {
                int row = wn * 64 + nj * 16 + ((lane >> 4) << 3) + (lane & 7);
                uint32_t bd = Bb + SWZ((uint32_t)(row * 128 + kk * 32 + (((lane >> 3) & 1) << 4)));
                asm volatile("ldmatrix.sync.aligned.m8n8.x4.shared.b16 {%0,%1,%2,%3},[%4];"
                    : "=r"(bfr[2*nj][0]), "=r"(bfr[2*nj][1]),
                      "=r"(bfr[2*nj+1][0]), "=r"(bfr[2*nj+1][1])
                    : "r"(bd));
            }
            #pragma unroll
            for (int mi = 0; mi < 2; mi++)
                #pragma unroll
                for (int ni = 0; ni < 8; ni++)
                    asm volatile("mma.sync.aligned.m16n8k16.row.col.f32.bf16.bf16.f32 "
                        "{%0,%1,%2,%3},{%4,%5,%6,%7},{%8,%9},{%0,%1,%2,%3};"
                        : "+f"(acc[mi][ni][0]), "+f"(acc[mi][ni][1]),
                          "+f"(acc[mi][ni][2]), "+f"(acc[mi][ni][3])
                        : "r"(af[mi][0]), "r"(af[mi][1]), "r"(af[mi][2]), "r"(af[mi][3]),
                          "r"(bfr[ni][0]), "r"(bfr[ni][1]));
        }
    }

    // ---- epilogue ----
    if (MODE == 0) {
        #pragma unroll
        for (int mi = 0; mi < 2; mi++) {
            long r0 = row0 + wm * 32 + mi * 16 + (lane >> 2);
            #pragma unroll
            for (int ni = 0; ni < 8; ni++) {
                int cc = wn * 64 + ni * 8 + ((lane & 3) << 1);
                float b0 = bias_s[cc], b1 = bias_s[cc + 1];
                float* c = acc[mi][ni];
                uint32_t p0 = bf2u(__floats2bfloat162_rn(gelu_exact(c[0] + b0), gelu_exact(c[1] + b1)));
                uint32_t p1 = bf2u(__floats2bfloat162_rn(gelu_exact(c[2] + b0), gelu_exact(c[3] + b1)));
                *(uint32_t*)(g_H + r0 * HID + col0 + cc) = p0;
                *(uint32_t*)(g_H + (r0 + 8) * HID + col0 + cc) = p1;
            }
        }
    } else {
        #pragma unroll
        for (int mi = 0; mi < 2; mi++) {
            float s0 = 0.f, s1 = 0.f;
            #pragma unroll
            for (int ni = 0; ni < 8; ni++) {
                int cc = wn * 64 + ni * 8 + ((lane & 3) << 1);
                float b0 = bias_s[cc], b1 = bias_s[cc + 1];
                float w0 = w2_s[cc], w1 = w2_s[cc + 1];
                float* c = acc[mi][ni];
                s0 += tanhf(c[0] + b0) * w0 + tanhf(c[1] + b1) * w1;
                s1 += tanhf(c[2] + b0) * w0 + tanhf(c[3] + b1) * w1;
            }
            s0 += __shfl_xor_sync(0xffffffffu, s0, 1);
            s0 += __shfl_xor_sync(0xffffffffu, s0, 2);
            s1 += __shfl_xor_sync(0xffffffffu, s1, 1);
            s1 += __shfl_xor_sync(0xffffffffu, s1, 2);
            if ((lane & 3) == 0) {
                int lr = wm * 32 + mi * 16 + (lane >> 2);
                sp[lr * 4 + wn] = s0;
                sp[(lr + 8) * 4 + wn] = s1;
            }
        }
        __syncthreads();
        if (tid < 128) {
            float sc = sp[tid * 4] + sp[tid * 4 + 1] + sp[tid * 4 + 2] + sp[tid * 4 + 3] + ba2p[0];
            long t = row0 + tid;
            g_scores_t[(t & 15) * MPER + (t >> 4)] = sc;
        }
    }
}

// ---------------- softmax stats, two-phase ------------------------------------
__global__ __launch_bounds__(256)
void stats_p1()
{
    int r = blockIdx.x, q = blockIdx.y, tid = threadIdx.x;
    __shared__ float red[256];
    const float* spt = g_scores_t + r * MPER + q * 512;
    float v0 = spt[tid], v1 = spt[tid + 256];
    red[tid] = fmaxf(v0, v1);
    __syncthreads();
    for (int s = 128; s; s >>= 1) { if (tid < s) red[tid] = fmaxf(red[tid], red[tid + s]); __syncthreads(); }
    float mx = red[0];
    __syncthreads();
    red[tid] = expf(v0 - mx) + expf(v1 - mx);
    __syncthreads();
    for (int s = 128; s; s >>= 1) { if (tid < s) red[tid] += red[tid + s]; __syncthreads(); }
    if (tid == 0) { g_pmax[r * 8 + q] = mx; g_psum[r * 8 + q] = red[0]; }
}

__global__ __launch_bounds__(128)
void stats_p2()
{
    __shared__ float m[128], s[128];
    int tid = threadIdx.x;
    m[tid] = g_pmax[tid]; s[tid] = g_psum[tid];
    __syncthreads();
    if (tid < NREG) {
        float M = -1e30f;
        #pragma unroll
        for (int j = 0; j < 8; j++) M = fmaxf(M, m[tid * 8 + j]);
        float S = 0.f;
        #pragma unroll
        for (int j = 0; j < 8; j++) S += s[tid * 8 + j] * expf(m[tid * 8 + j] - M);
        g_stats[tid] = M; g_stats[16 + tid] = S;
    }
}

// ---------------- pooling: coalesced partials over token blocks ---------------
__global__ __launch_bounds__(256)
void pool_partial()
{
    __shared__ float wts[128];
    int blk = blockIdx.x, tid = threadIdx.x;
    long base = (long)blk * 128;
    if (tid < 128) {
        long t = base + tid;
        int r = (int)(t & 15);
        wts[tid] = expf(g_scores_t[r * MPER + (t >> 4)] - g_stats[r]);
    }
    __syncthreads();
    int c = tid;
    #pragma unroll 1
    for (int r = 0; r < NREG; r++) {
        float a0 = 0.f, a1 = 0.f;
        #pragma unroll
        for (int i = 0; i < 8; i++) {
            int lr = r + i * 16;
            uint32_t u = *(const uint32_t*)(g_H + (base + lr) * HID + 2 * c);
            __nv_bfloat162 h2 = *reinterpret_cast<__nv_bfloat162*>(&u);
            float w = wts[lr];
            a0 += w * __bfloat162float(h2.x);
            a1 += w * __bfloat162float(h2.y);
        }
        g_pp[(blk * NREG + r) * 256 + c] = make_float2(a0, a1);
    }
}

__global__ __launch_bounds__(256)
void pool_reduce4()
{
    int r = blockIdx.x, q = blockIdx.y, c = threadIdx.x;
    float a0 = 0.f, a1 = 0.f;
    #pragma unroll 4
    for (int blk = q * 128; blk < q * 128 + 128; blk++) {
        float2 v = g_pp[(blk * NREG + r) * 256 + c];
        a0 += v.x; a1 += v.y;
    }
    g_pp2[(q * NREG + r) * 256 + c] = make_float2(a0, a1);
}

// ---------------- slide encoder + attention score, one CTA per region ---------
__global__ __launch_bounds__(512)
void slide_enc(const float* __restrict__ Ws,  const float* __restrict__ bs,
               const float* __restrict__ Wsa1,const float* __restrict__ bsa1,
               const float* __restrict__ Wsa2,const float* __restrict__ bsa2)
{
    __shared__ float rf[HID];
    __shared__ float se[HID];
    __shared__ float part[512];
    int r = blockIdx.x, tid = threadIdx.x;

    {
        float inv = 1.0f / g_stats[16 + r];
        int cp = tid >> 1;
        float a = 0.f;
        #pragma unroll
        for (int q = 0; q < 4; q++) {
            float2 v = g_pp2[(q * NREG + r) * 256 + cp];
            a += (tid & 1) ? v.y : v.x;
        }
        rf[tid] = a * inv;
    }
    __syncthreads();

    float acc = 0.f;
    #pragma unroll 8
    for (int k = 0; k < HID; k++) acc += rf[k] * Ws[k * HID + tid];
    float sev = gelu_exact(acc + bs[tid]);
    se[tid] = sev;
    g_se[r * HID + tid] = sev;
    __syncthreads();

    int j = tid & 255, h = tid >> 8;
    float p = 0.f;
    #pragma unroll 8
    for (int k = h * 256; k < h * 256 + 256; k++) p += se[k] * Wsa1[k * HHALF + j];
    part[tid] = p;
    __syncthreads();
    if (tid < 256)
        part[tid] = tanhf(part[tid] + part[tid + 256] + bsa1[tid]) * Wsa2[tid];
    __syncthreads();
    for (int s = 128; s; s >>= 1) { if (tid < s) part[tid] += part[tid + s]; __syncthreads(); }
    if (tid == 0) g_sattn[r] = part[0] + bsa2[0];
}

// ---------------- final: softmax-16 + slide_rep + classifier ------------------
__global__ __launch_bounds__(512)
void tail_final(const float* __restrict__ Wc1, const float* __restrict__ bc1,
                const float* __restrict__ Wc2, const float* __restrict__ bc2,
                float* __restrict__ out)
{
    __shared__ float w[NREG];
    __shared__ float srep[HID];
    __shared__ float c1[HHALF];
    __shared__ float red[64];
    int tid = threadIdx.x;

    if (tid == 0) {
        float mx = -1e30f;
        for (int r = 0; r < NREG; r++) mx = fmaxf(mx, g_sattn[r]);
        float s = 0.f;
        for (int r = 0; r < NREG; r++) { w[r] = expf(g_sattn[r] - mx); s += w[r]; }
        for (int r = 0; r < NREG; r++) w[r] /= s;
    }
    __syncthreads();

    float a = 0.f;
    #pragma unroll
    for (int r = 0; r < NREG; r++) a += w[r] * g_se[r * HID + tid];
    srep[tid] = a;
    __syncthreads();

    if (tid < HHALF) {
        float acc = 0.f;
        #pragma unroll 8
        for (int k = 0; k < HID; k++) acc += srep[k] * Wc1[k * HHALF + tid];
        c1[tid] = gelu_exact(acc + bc1[tid]);
    }
    __syncthreads();

    if (tid < 64) {
        int o = tid & 1, p = tid >> 1;
        float acc = 0.f;
        for (int k = p; k < HHALF; k += 32) acc += c1[k] * Wc2[k * 2 + o];
        red[tid] = acc;
    }
    __syncthreads();
    if (tid < 2) {
        float acc = bc2[tid];
        #pragma unroll
        for (int p = 0; p < 32; p++) acc += red[p * 2 + tid];
        out[tid] = acc;
    }
}

// ---------------- launch ------------------------------------------------------
extern "C" void kernel_launch(void* const* d_in, const int* in_sizes, int n_in,
                              void* d_out, int out_size)
{
    const float* emb  = (const float*)d_in[0];
    const float* W1   = (const float*)d_in[1];
    const float* b1   = (const float*)d_in[2];
    const float* Wa1  = (const float*)d_in[3];
    const float* ba1  = (const float*)d_in[4];
    const float* Wa2  = (const float*)d_in[5];
    const float* ba2  = (const float*)d_in[6];
    const float* Ws   = (const float*)d_in[7];
    const float* bs   = (const float*)d_in[8];
    const float* Wsa1 = (const float*)d_in[9];
    const float* bsa1 = (const float*)d_in[10];
    const float* Wsa2 = (const float*)d_in[11];
    const float* bsa2 = (const float*)d_in[12];
    const float* Wc1  = (const float*)d_in[13];
    const float* bc1  = (const float*)d_in[14];
    const float* Wc2  = (const float*)d_in[15];
    const float* bc2  = (const float*)d_in[16];
    float* out = (float*)d_out;

    cudaFuncSetAttribute(mma_gemm<DIM, 0>, cudaFuncAttributeMaxDynamicSharedMemorySize, SMEM_REQ);
    cudaFuncSetAttribute(mma_gemm<HID, 1>, cudaFuncAttributeMaxDynamicSharedMemorySize, SMEM_REQ);

    __nv_bfloat16 *wt1, *wt2;
    cudaGetSymbolAddress((void**)&wt1, g_Wt1);
    cudaGetSymbolAddress((void**)&wt2, g_Wt2);
    transpose_conv<<<dim3(HID / 32, DIM / 32), 256>>>(W1, wt1, DIM, HID);
    transpose_conv<<<dim3(HHALF / 32, HID / 32), 256>>>(Wa1, wt2, HID, HHALF);

    // K1: region encoder (65536x1024 @ 1024x512) + GELU -> g_H
    mma_gemm<DIM, 0><<<dim3(2, NTOK / 128), 512, SMEM_REQ>>>(emb, b1, nullptr, nullptr);
    // K2: attention hidden (65536x512 @ 512x256) + fused tanh-dot -> direct scores
    mma_gemm<HID, 1><<<dim3(1, NTOK / 128), 512, SMEM_REQ>>>(nullptr, ba1, Wa2, ba2);

    stats_p1<<<dim3(NREG, 8), 256>>>();
    stats_p2<<<1, 128>>>();
    pool_partial<<<512, 256>>>();
    pool_reduce4<<<dim3(NREG, 4), 256>>>();
    slide_enc<<<NREG, 512>>>(Ws, bs, Wsa1, bsa1, Wsa2, bsa2);
    tail_final<<<1, 512>>>(Wc1, bc1, Wc2, bc2, out);
}